// round 11
// baseline (speedup 1.0000x reference)
#include <cuda_runtime.h>
#include <cuda_bf16.h>
#include <float.h>

#define Bn 128
#define On 1024
#define In 1024
#define EPSc 1e-7f
#define L2E 1.4426950408889634f
#define CUT_NATS 20.794415417f   // 30*ln2: drop softmax terms with weight < 2^-30
#define CAP 64                   // per-i candidate capacity (dense fallback beyond)

// Scratch (no allocs allowed)
__device__ float    g_c2_im[In * On];    // C^2, i-major [i][o]
__device__ float    g_data_im[In * Bn];  // data transposed [i][b]
__device__ unsigned g_min[In];           // min over o of C^2[:,i]
__device__ float    g_T[In];             // keep-threshold per i
__device__ int      g_cnt[In];           // candidates per i
__device__ float2   g_list[In][CAP];     // {o as int-bits, c2}

__device__ __forceinline__ float rsq(float x) {
    float r;
    asm("rsqrt.approx.ftz.f32 %0, %1;" : "=f"(r) : "f"(x));
    return r;
}
__device__ __forceinline__ float ex2(float x) {
    float r;
    asm("ex2.approx.ftz.f32 %0, %1;" : "=f"(r) : "f"(x));
    return r;
}

// ---------------- kinit: zero out + init min/cnt (replaces memset) ----------------
__global__ void kinit(float* __restrict__ out) {
    int idx = blockIdx.x * 256 + threadIdx.x;
    out[idx] = 0.f;                           // 128K threads cover Bn*On exactly
    if (idx < In) { g_min[idx] = 0x7F800000u; g_cnt[idx] = 0; }
}

// ---------------- kprep: C^2 transpose + per-i min + data transpose ----------------
// Keeps IEEE div.rn for ix/iy, ox/oy — C is cancellation-amplified.
__global__ void kprep(const float* __restrict__ data,
                      const float* __restrict__ ix, const float* __restrict__ iy,
                      const float* __restrict__ ox, const float* __restrict__ oy,
                      const float* __restrict__ la, const float* __restrict__ lm) {
    __shared__ float tile[32][33];
    int tx = threadIdx.x & 31;
    int ty = threadIdx.x >> 5;

    if (blockIdx.x < 1024) {
        int ob  = (blockIdx.x & 31) * 32;   // o tile base
        int ibt = (blockIdx.x >> 5) * 32;   // i tile base
#pragma unroll
        for (int k = 0; k < 4; k++) {
            int o = ob + ty + k * 8;
            int idx = o * In + ibt + tx;    // coalesced over tx
            float c = (ix[idx] / iy[idx] + la[idx]) * (1.0f + lm[idx]) - ox[idx] / oy[idx];
            tile[ty + k * 8][tx] = c * c;
        }
        __syncthreads();
#pragma unroll
        for (int k = 0; k < 4; k++) {
            int il = ty + k * 8;            // fixed i per warp
            float v = tile[tx][il];         // tx = o within tile
            g_c2_im[(ibt + il) * In + ob + tx] = v;
            float mn = v;
#pragma unroll
            for (int s = 16; s; s >>= 1) mn = fminf(mn, __shfl_xor_sync(0xffffffffu, mn, s));
            if (tx == 0) atomicMin(&g_min[ibt + il], __float_as_uint(mn));
        }
    } else {
        int tb = blockIdx.x - 1024;         // data transpose: [128,1024]->[1024,128]
        int bb = (tb & 3) * 32;
        int ib = (tb >> 2) * 32;
#pragma unroll
        for (int k = 0; k < 4; k++)
            tile[ty + k * 8][tx] = data[(bb + ty + k * 8) * In + ib + tx];
        __syncthreads();
#pragma unroll
        for (int k = 0; k < 4; k++) {
            int il = ty + k * 8;
            g_data_im[(ib + il) * Bn + bb + tx] = tile[tx][il];
        }
    }
}

// ---------------- kthresh: T[i] = max_b keep(b,i) ----------------
// warp per i; lane r handles b = lane + 32r.
__global__ void __launch_bounds__(256) kthresh() {
    int t = threadIdx.x, lane = t & 31, warp = t >> 5;
    int i = blockIdx.x * 8 + warp;
    float c2min = __uint_as_float(g_min[i]);
    const float* dcol = g_data_im + (size_t)i * Bn;

    float kmax = 0.f;
#pragma unroll
    for (int r = 0; r < 4; r++) {
        float d = dcol[lane + 32 * r];
        float g = 1.0f / (1.0f + __expf(-d));
        float g2 = g * g;
        float smax = rsq(fmaf(c2min, g2, EPSc));
        float q = smax - CUT_NATS;
        float keep = (q > 0.f) ? (1.0f / (q * q) - EPSc) / g2 : FLT_MAX;
        kmax = fmaxf(kmax, keep);
    }
#pragma unroll
    for (int s = 16; s; s >>= 1) kmax = fmaxf(kmax, __shfl_xor_sync(0xffffffffu, kmax, s));
    if (lane == 0) g_T[i] = kmax;
}

// ---------------- kscan: streaming candidate selection ----------------
// 256K independent threads, one float4 each — pure bandwidth, no chains.
__global__ void __launch_bounds__(256) kscan() {
    int f = blockIdx.x * 256 + threadIdx.x;     // float4 index into c2_im
    int i = f >> 8;                              // 256 float4 per row
    int o0 = (f & 255) * 4;
    float T = g_T[i];                            // L1/L2-cached broadcast
    float4 v = ((const float4*)g_c2_im)[f];

    if (v.x <= T) { int p = atomicAdd(&g_cnt[i], 1); if (p < CAP) g_list[i][p] = make_float2(__int_as_float(o0),     v.x); }
    if (v.y <= T) { int p = atomicAdd(&g_cnt[i], 1); if (p < CAP) g_list[i][p] = make_float2(__int_as_float(o0 + 1), v.y); }
    if (v.z <= T) { int p = atomicAdd(&g_cnt[i], 1); if (p < CAP) g_list[i][p] = make_float2(__int_as_float(o0 + 2), v.z); }
    if (v.w <= T) { int p = atomicAdd(&g_cnt[i], 1); if (p < CAP) g_list[i][p] = make_float2(__int_as_float(o0 + 3), v.w); }
}

// ---------------- keval: evaluate candidates, accumulate out ----------------
// warp per i; lane r handles b = lane + 32r (4 b's per lane).
__global__ void __launch_bounds__(256) keval(float* __restrict__ out) {
    int t = threadIdx.x, lane = t & 31, warp = t >> 5;
    int i = blockIdx.x * 8 + warp;

    int cnt = g_cnt[i];
    float c2min = __uint_as_float(g_min[i]);
    const float* dcol = g_data_im + (size_t)i * Bn;

    float dd[4], g2[4], Bm[4], S[4] = {0.f, 0.f, 0.f, 0.f};
#pragma unroll
    for (int r = 0; r < 4; r++) {
        dd[r] = dcol[lane + 32 * r];
        float g = 1.0f / (1.0f + __expf(-dd[r]));
        g2[r] = g * g;
        Bm[r] = -rsq(fmaf(c2min, g2[r], EPSc)) * L2E;
    }

    if (cnt <= CAP) {
        // sparse path: every lane reads the same tiny list (broadcast loads)
        for (int k = 0; k < cnt; k++) {
            float c2 = g_list[i][k].y;
#pragma unroll
            for (int r = 0; r < 4; r++)
                S[r] += ex2(fmaf(rsq(fmaf(c2, g2[r], EPSc)), L2E, Bm[r]));
        }
        float coef[4];
#pragma unroll
        for (int r = 0; r < 4; r++) coef[r] = __fdividef(dd[r], S[r]);
        for (int k = 0; k < cnt; k++) {
            float2 ent = g_list[i][k];
            int o = __float_as_int(ent.x);
            float c2 = ent.y;
#pragma unroll
            for (int r = 0; r < 4; r++) {
                float e = ex2(fmaf(rsq(fmaf(c2, g2[r], EPSc)), L2E, Bm[r]));
                atomicAdd(&out[(size_t)(lane + 32 * r) * On + o], coef[r] * e);
            }
        }
    } else {
        // dense fallback — correct for any data; statistically never taken
        const float* row = g_c2_im + (size_t)i * In;
        for (int k = 0; k < In; k++) {
            float c2 = row[k];
#pragma unroll
            for (int r = 0; r < 4; r++)
                S[r] += ex2(fmaf(rsq(fmaf(c2, g2[r], EPSc)), L2E, Bm[r]));
        }
        float coef[4];
#pragma unroll
        for (int r = 0; r < 4; r++) coef[r] = __fdividef(dd[r], S[r]);
        for (int k = 0; k < In; k++) {
            float c2 = row[k];
#pragma unroll
            for (int r = 0; r < 4; r++) {
                float e = ex2(fmaf(rsq(fmaf(c2, g2[r], EPSc)), L2E, Bm[r]));
                atomicAdd(&out[(size_t)(lane + 32 * r) * On + k], coef[r] * e);
            }
        }
    }
}

extern "C" void kernel_launch(void* const* d_in, const int* in_sizes, int n_in,
                              void* d_out, int out_size) {
    const float* data = (const float*)d_in[0];
    const float* ix   = (const float*)d_in[1];
    const float* iy   = (const float*)d_in[2];
    const float* ox   = (const float*)d_in[3];
    const float* oy   = (const float*)d_in[4];
    const float* la   = (const float*)d_in[5];
    const float* lm   = (const float*)d_in[6];
    float* out = (float*)d_out;

    kinit<<<(Bn * On) / 256, 256>>>(out);
    kprep<<<1152, 256>>>(data, ix, iy, ox, oy, la, lm);
    kthresh<<<In / 8, 256>>>();
    kscan<<<(In * On / 4) / 256, 256>>>();
    keval<<<In / 8, 256>>>(out);
}

// round 12
// speedup vs baseline: 1.7912x; 1.7912x over previous
#include <cuda_runtime.h>
#include <cuda_bf16.h>
#include <float.h>

#define Bn 128
#define On 1024
#define In 1024
#define EPSc 1e-7f
#define L2E 1.4426950408889634f
#define CUT_NATS 20.794415417f   // 30*ln2: drop softmax terms with weight < 2^-30
#define W 8                      // warps (=i's) per kmega block
#define CAP 96                   // per-warp candidate capacity (dense fallback beyond)

// Scratch (no allocs allowed) — fully rewritten every run, no cross-run state.
__device__ float g_c2_im[In * On];    // C^2, i-major [i][o]
__device__ float g_data_im[In * Bn];  // data transposed [i][b]

__device__ __forceinline__ float rsq(float x) {
    float r;
    asm("rsqrt.approx.ftz.f32 %0, %1;" : "=f"(r) : "f"(x));
    return r;
}
__device__ __forceinline__ float ex2(float x) {
    float r;
    asm("ex2.approx.ftz.f32 %0, %1;" : "=f"(r) : "f"(x));
    return r;
}

// ---------------- kprep: C^2 transpose + data transpose + out zeroing ----------------
// Launch 1 of 2. Keeps IEEE div.rn for ix/iy, ox/oy — C is cancellation-amplified.
__global__ void kprep(float* __restrict__ out,
                      const float* __restrict__ data,
                      const float* __restrict__ ix, const float* __restrict__ iy,
                      const float* __restrict__ ox, const float* __restrict__ oy,
                      const float* __restrict__ la, const float* __restrict__ lm) {
    __shared__ float tile[32][33];
    int tx = threadIdx.x & 31;
    int ty = threadIdx.x >> 5;

    if (blockIdx.x < 1024) {
        int ob  = (blockIdx.x & 31) * 32;   // o tile base
        int ibt = (blockIdx.x >> 5) * 32;   // i tile base
#pragma unroll
        for (int k = 0; k < 4; k++) {
            int o = ob + ty + k * 8;
            int idx = o * In + ibt + tx;    // coalesced over tx
            float c = (ix[idx] / iy[idx] + la[idx]) * (1.0f + lm[idx]) - ox[idx] / oy[idx];
            tile[ty + k * 8][tx] = c * c;
        }
        __syncthreads();
#pragma unroll
        for (int k = 0; k < 4; k++) {
            int il = ty + k * 8;
            g_c2_im[(ibt + il) * In + ob + tx] = tile[tx][il];
        }
    } else {
        // data transpose [128,1024] -> [1024,128], plus output zeroing
        int tb = blockIdx.x - 1024;         // 0..127
        ((float4*)out)[tb * 256 + threadIdx.x] = make_float4(0.f, 0.f, 0.f, 0.f);
        int bb = (tb & 3) * 32;
        int ib = (tb >> 2) * 32;
#pragma unroll
        for (int k = 0; k < 4; k++)
            tile[ty + k * 8][tx] = data[(bb + ty + k * 8) * In + ib + tx];
        __syncthreads();
#pragma unroll
        for (int k = 0; k < 4; k++) {
            int il = ty + k * 8;
            g_data_im[(ib + il) * Bn + bb + tx] = tile[tx][il];
        }
    }
}

// ---------------- kmega: warp-per-i sparse softmax (launch 2 of 2) ----------------
// Warp holds the full C^2 row (32 floats/lane): local min, threshold T via
// warp max, ballot/popc compaction (no serialized atomics), then each lane
// evaluates the tiny candidate list for its 4 b's and scatter-adds.
__global__ void __launch_bounds__(256) kmega(float* __restrict__ out) {
    __shared__ int   s_o[W][CAP];
    __shared__ float s_c2[W][CAP];

    int t = threadIdx.x, lane = t & 31, warp = t >> 5;
    int i = blockIdx.x * W + warp;          // grid = 128 -> single wave
    unsigned lmask = (1u << lane) - 1u;

    // --- row C^2[:,i] into registers ---
    const float4* src = (const float4*)(g_c2_im + (size_t)i * In);
    float4 c[8];
#pragma unroll
    for (int j = 0; j < 8; j++) c[j] = src[lane + 32 * j];

    // --- warp min -> c2min ---
    float mn = FLT_MAX;
#pragma unroll
    for (int j = 0; j < 8; j++)
        mn = fminf(mn, fminf(fminf(c[j].x, c[j].y), fminf(c[j].z, c[j].w)));
#pragma unroll
    for (int s = 16; s; s >>= 1) mn = fminf(mn, __shfl_xor_sync(0xffffffffu, mn, s));
    float c2min = mn;

    // --- per-b scalars (lane r-slot: b = lane + 32r) + keep threshold ---
    const float* dcol = g_data_im + (size_t)i * Bn;
    float dd[4], g2[4], Bm[4];
    float kmax = 0.f;
#pragma unroll
    for (int r = 0; r < 4; r++) {
        dd[r] = dcol[lane + 32 * r];        // coalesced
        float g = 1.0f / (1.0f + __expf(-dd[r]));
        g2[r] = g * g;
        float smax = rsq(fmaf(c2min, g2[r], EPSc));
        Bm[r] = -smax * L2E;
        float q = smax - CUT_NATS;
        float keep = (q > 0.f) ? (1.0f / (q * q) - EPSc) / g2[r] : FLT_MAX;
        kmax = fmaxf(kmax, keep);
    }
#pragma unroll
    for (int s = 16; s; s >>= 1) kmax = fmaxf(kmax, __shfl_xor_sync(0xffffffffu, kmax, s));
    float T = kmax;

    // --- ballot/popc compaction of {o : C^2 <= T} (no serialized atomics) ---
    int base = 0;
#pragma unroll
    for (int j = 0; j < 8; j++) {
        float vv[4] = {c[j].x, c[j].y, c[j].z, c[j].w};
#pragma unroll
        for (int m = 0; m < 4; m++) {
            bool pred = (vv[m] <= T);
            unsigned bal = __ballot_sync(0xffffffffu, pred);
            if (pred) {
                int pos = base + __popc(bal & lmask);
                if (pos < CAP) {
                    s_o[warp][pos]  = 4 * (lane + 32 * j) + m;
                    s_c2[warp][pos] = vv[m];
                }
            }
            base += __popc(bal);
        }
    }
    int cnt = base;                          // warp-uniform
    __syncwarp();

    if (cnt <= CAP) {
        // --- sparse path: lanes walk the shared tiny list (LDS broadcast) ---
        float S[4] = {0.f, 0.f, 0.f, 0.f};
        for (int k = 0; k < cnt; k++) {
            float c2 = s_c2[warp][k];
#pragma unroll
            for (int r = 0; r < 4; r++)
                S[r] += ex2(fmaf(rsq(fmaf(c2, g2[r], EPSc)), L2E, Bm[r]));
        }
        float coef[4];
#pragma unroll
        for (int r = 0; r < 4; r++) coef[r] = __fdividef(dd[r], S[r]);
        for (int k = 0; k < cnt; k++) {
            int o = s_o[warp][k];
            float c2 = s_c2[warp][k];
#pragma unroll
            for (int r = 0; r < 4; r++) {
                float e = ex2(fmaf(rsq(fmaf(c2, g2[r], EPSc)), L2E, Bm[r]));
                atomicAdd(&out[(size_t)(lane + 32 * r) * On + o], coef[r] * e);
            }
        }
    } else {
        // --- dense fallback: re-read row from gmem (cold path; keeps c[] dead) ---
        const float* row = g_c2_im + (size_t)i * In;
        float S[4] = {0.f, 0.f, 0.f, 0.f};
        for (int k = 0; k < In; k++) {
            float c2 = row[k];
#pragma unroll
            for (int r = 0; r < 4; r++)
                S[r] += ex2(fmaf(rsq(fmaf(c2, g2[r], EPSc)), L2E, Bm[r]));
        }
        float coef[4];
#pragma unroll
        for (int r = 0; r < 4; r++) coef[r] = __fdividef(dd[r], S[r]);
        for (int k = 0; k < In; k++) {
            float c2 = row[k];
#pragma unroll
            for (int r = 0; r < 4; r++) {
                float e = ex2(fmaf(rsq(fmaf(c2, g2[r], EPSc)), L2E, Bm[r]));
                atomicAdd(&out[(size_t)(lane + 32 * r) * On + k], coef[r] * e);
            }
        }
    }
}

extern "C" void kernel_launch(void* const* d_in, const int* in_sizes, int n_in,
                              void* d_out, int out_size) {
    const float* data = (const float*)d_in[0];
    const float* ix   = (const float*)d_in[1];
    const float* iy   = (const float*)d_in[2];
    const float* ox   = (const float*)d_in[3];
    const float* oy   = (const float*)d_in[4];
    const float* la   = (const float*)d_in[5];
    const float* lm   = (const float*)d_in[6];
    float* out = (float*)d_out;

    kprep<<<1152, 256>>>(out, data, ix, iy, ox, oy, la, lm);
    kmega<<<In / W, 256>>>(out);
}